// round 13
// baseline (speedup 1.0000x reference)
#include <cuda_runtime.h>
#include <cstdint>
#include <cstddef>

// ---------------------------------------------------------------------------
// Problem constants
// ---------------------------------------------------------------------------
#define B_ROWS 8192
#define MDIM   256
#define NDIM   512
#define NITER  16

// Persistent-CTA: 128 CTAs x 512 threads; CTA owns 64 rows for all iterations.
// u-space recurrence: u' = sigma(u) @ Bu^T + WyD,  d_t = sigma(u) @ G2^T.
// Both share A = sigma(u) (s2, resident in smem). One fused pass per iteration
// over Bcat = [G2 ; Bu] (1024 x 512), 4 chunks of 256 cols, K=512.
#define ROWS 64
#define NC   256
#define KC   32            // K elems per block = 16 uint2 k-pairs = 128B row
#define KP   16            // k-pairs per block

#define S_U2   (ROWS * 256)          // 16384 uint2: persistent packed s tile
#define BST_U2 (NC * KP)             // 4096 uint2 per B stage
#define NBST   3                     // B pipeline stages
#define SMEM_BYTES ((S_U2 + NBST * BST_U2) * 8)   // 229376
#define PE 260                        // epilogue fp32 staging pitch

// ---------------------------------------------------------------------------
// Device scratch (static __device__ arrays: allocation-free rule)
// ---------------------------------------------------------------------------
__device__ __align__(1024) uint2 g_Bcatp[1024 * (NDIM / 2)];       // [G2 ; Bu] packed
__device__ __align__(1024) uint2 g_GWp[NDIM * MDIM / 2];           // packed D@W
__device__ __align__(1024) uint2 g_yp[(size_t)B_ROWS * MDIM / 2];  // packed y
__device__ __align__(1024) float g_WyD[(size_t)B_ROWS * NDIM];     // fp32 addend
__device__ __align__(1024) float g_Ulo[(size_t)B_ROWS * (NDIM/2)]; // u cols 0-255 scratch
__device__ __align__(1024) float g_G1f[NDIM * NDIM];               // fp32 D@S temp

// ---------------------------------------------------------------------------
// PTX helpers (sm_80-level: portable to sm_103 base target)
// ---------------------------------------------------------------------------
__device__ __forceinline__ void cp_async16(uint32_t dst_smem, const void* src) {
    asm volatile("cp.async.cg.shared.global [%0], [%1], 16;"
                 :: "r"(dst_smem), "l"(src) : "memory");
}
__device__ __forceinline__ void cp_commit() {
    asm volatile("cp.async.commit_group;" ::: "memory");
}
template <int N>
__device__ __forceinline__ void cp_wait() {
    asm volatile("cp.async.wait_group %0;" :: "n"(N) : "memory");
}
// pack (u0,u1) into bf16x2 hi + bf16x2 lo (lower half = u0)
__device__ __forceinline__ uint2 pack_split(float u0, float u1) {
    uint32_t hi;
    asm("cvt.rn.bf16x2.f32 %0, %1, %2;" : "=r"(hi) : "f"(u1), "f"(u0));
    float h0 = __uint_as_float(hi << 16);
    float h1 = __uint_as_float(hi & 0xFFFF0000u);
    uint32_t lo;
    asm("cvt.rn.bf16x2.f32 %0, %1, %2;" : "=r"(lo) : "f"(u1 - h1), "f"(u0 - h0));
    return make_uint2(hi, lo);
}
__device__ __forceinline__ void mma_bf16(float* c, const uint32_t* a, const uint32_t* b) {
    asm volatile(
        "mma.sync.aligned.m16n8k16.row.col.f32.bf16.bf16.f32 "
        "{%0,%1,%2,%3},{%4,%5,%6,%7},{%8,%9},{%0,%1,%2,%3};"
        : "+f"(c[0]), "+f"(c[1]), "+f"(c[2]), "+f"(c[3])
        : "r"(a[0]), "r"(a[1]), "r"(a[2]), "r"(a[3]), "r"(b[0]), "r"(b[1]));
}
__device__ __forceinline__ float softthr(float u, float th) {
    return fmaxf(u - th, 0.f) - fmaxf(-u - th, 0.f);
}

// ---------------------------------------------------------------------------
// Precompute kernels
// ---------------------------------------------------------------------------
// C[n][m] = sum_j A[n][j] * X[j][m]   (fp32 out)
__global__ void k_small_gemm_f32(const float* __restrict__ A, const float* __restrict__ X,
                                 float* __restrict__ C, int Mcols, int J) {
    __shared__ float As[16][17];
    __shared__ float Xs[16][17];
    int tx = threadIdx.x, ty = threadIdx.y;
    int m = blockIdx.x * 16 + tx;
    int n = blockIdx.y * 16 + ty;
    float acc = 0.f;
    for (int j0 = 0; j0 < J; j0 += 16) {
        As[ty][tx] = A[(size_t)n * J + j0 + tx];
        Xs[ty][tx] = X[(size_t)(j0 + ty) * Mcols + m];
        __syncthreads();
#pragma unroll
        for (int jj = 0; jj < 16; jj++) acc += As[ty][jj] * Xs[jj][tx];
        __syncthreads();
    }
    C[(size_t)n * Mcols + m] = acc;
}

// Cp[n][m-pair] = pack( sum_j A[n][j]*X[j][m] )  (pack along m)
__global__ void k_small_gemm_pack(const float* __restrict__ A, const float* __restrict__ X,
                                  uint2* __restrict__ Cp, int Mcols, int J) {
    __shared__ float As[16][17];
    __shared__ float Xs[16][17];
    int tx = threadIdx.x, ty = threadIdx.y;
    int m = blockIdx.x * 16 + tx;
    int n = blockIdx.y * 16 + ty;
    float acc = 0.f;
    for (int j0 = 0; j0 < J; j0 += 16) {
        As[ty][tx] = A[(size_t)n * J + j0 + tx];
        Xs[ty][tx] = X[(size_t)(j0 + ty) * Mcols + m];
        __syncthreads();
#pragma unroll
        for (int jj = 0; jj < 16; jj++) acc += As[ty][jj] * Xs[jj][tx];
        __syncthreads();
    }
    float other = __shfl_xor_sync(0xffffffffu, acc, 1);
    if (!(tx & 1))
        Cp[(size_t)n * (Mcols / 2) + m / 2] = pack_split(acc, other);
}

// Cp[i][j-pair] = pack( sum_k A[i][k]*Bm[j][k] )  (A,Bm: 512x512 row-major)
__global__ void k_abt_pack(const float* __restrict__ A, const float* __restrict__ Bm,
                           uint2* __restrict__ Cp) {
    __shared__ float As[16][17];
    __shared__ float Bs[16][17];
    int tx = threadIdx.x, ty = threadIdx.y;
    int i = blockIdx.y * 16 + ty;
    int j = blockIdx.x * 16 + tx;
    float acc = 0.f;
    for (int k0 = 0; k0 < NDIM; k0 += 16) {
        As[ty][tx] = A[(size_t)i * NDIM + k0 + tx];
        Bs[ty][tx] = Bm[(size_t)(blockIdx.x * 16 + ty) * NDIM + k0 + tx];
        __syncthreads();
#pragma unroll
        for (int kk = 0; kk < 16; kk++) acc += As[ty][kk] * Bs[tx][kk];
        __syncthreads();
    }
    float other = __shfl_xor_sync(0xffffffffu, acc, 1);
    if (!(tx & 1))
        Cp[(size_t)i * (NDIM / 2) + j / 2] = pack_split(acc, other);
}

// G2p[n][kp] = pack( D[2kp][n], D[2kp+1][n] )
__global__ void k_transpose_pack(const float* __restrict__ D, uint2* __restrict__ G2p) {
    int kp = blockIdx.x * 16 + threadIdx.x;
    int n  = blockIdx.y * 16 + threadIdx.y;
    float u0 = D[(size_t)(2 * kp) * NDIM + n];
    float u1 = D[(size_t)(2 * kp + 1) * NDIM + n];
    G2p[(size_t)n * (NDIM / 2) + kp] = pack_split(u0, u1);
}

// dst[i] = pack(src[2i], src[2i+1])
__global__ void k_split_pack(const float* __restrict__ src, uint2* __restrict__ dst) {
    size_t i = (size_t)blockIdx.x * blockDim.x + threadIdx.x;
    float2 v = ((const float2*)src)[i];
    dst[i] = pack_split(v.x, v.y);
}

// ---------------------------------------------------------------------------
// Persistent ISTA kernel. 16 warps = 2(M) x 8(N), warp tile 32x32.
// ---------------------------------------------------------------------------
__global__ void __launch_bounds__(512, 1) k_ista(
    const float* __restrict__ thr_p, float* __restrict__ out,
    const uint2* __restrict__ Bcatp, const uint2* __restrict__ GWp,
    const uint2* __restrict__ yp, float* __restrict__ WyD,
    float* __restrict__ Ulo)
{
    extern __shared__ uint2 smu[];
    uint2* s2   = smu;                         // 64 x 256 packed s (swizzled)
    uint2* BstU = smu + S_U2;                  // 3 x 4096
    float* est  = (float*)BstU;                // epilogue fp32 staging overlay

    const int tid  = threadIdx.x;
    const int lane = tid & 31;
    const int warp = tid >> 5;
    const int wM = warp & 1;
    const int wN = warp >> 1;
    const int lr = lane >> 2;
    const int lc = lane & 3;
    const int r0 = blockIdx.x * ROWS;
    const float th = thr_p[0];
    const size_t slab = (size_t)B_ROWS * NDIM;

    // d0 = 0
    for (int i = tid; i < ROWS * (NDIM / 4); i += 512) {
        int r = i >> 7, c4 = i & 127;
        *(float4*)&out[(size_t)(r0 + r) * NDIM + c4 * 4] = make_float4(0, 0, 0, 0);
    }

    // ---- B stage fill (16B = 2 uint2; XOR swizzle within 16-uint2 rows) ----
    auto fillB = [&](int st, const uint2* Bg, int ldbp, int kb) {
#pragma unroll
        for (int i = 0; i < 4; ++i) {
            int ch = tid + i * 512;
            int r = ch >> 3, c2 = ch & 7;
            int cs = (c2 * 2) ^ ((r & 3) << 2);
            uint32_t d = (uint32_t)__cvta_generic_to_shared(&BstU[st * BST_U2 + r * KP + cs]);
            cp_async16(d, Bg + (size_t)r * ldbp + kb * KP + c2 * 2);
        }
    };
    // ---- prestep A stages overlay: s2 rows 0-15, second halves (cp 128-255) ----
    auto a_idx = [&](int st, int flat) {
        return (st * 8 + (flat >> 7)) * 256 + 128 + (flat & 127);
    };
    auto fillA_pre = [&](int st, const uint2* Ag, int kb) {
        int r = tid >> 3, c2 = tid & 7;
        int cs = (c2 * 2) ^ ((r & 3) << 2);
        uint32_t d = (uint32_t)__cvta_generic_to_shared(&s2[a_idx(st, r * KP + cs)]);
        cp_async16(d, Ag + (size_t)r * (MDIM / 2) + kb * KP + c2 * 2);
    };

    // ---- one k-block of 3-term bf16 MMAs ----
    auto mma_block = [&](auto getA, const uint2* sB, float (&c)[2][4][4]) {
#pragma unroll
        for (int ks = 0; ks < 2; ++ks) {
            const int kb0 = ks * 8 + lc;
            uint32_t ah[2][4], al[2][4], bh[4][2], bl[4][2];
#pragma unroll
            for (int mt = 0; mt < 2; ++mt) {
                const int rb = wM * 32 + mt * 16 + lr;
                uint2 v0 = getA(rb,     kb0);
                uint2 v1 = getA(rb + 8, kb0);
                uint2 v2 = getA(rb,     kb0 + 4);
                uint2 v3 = getA(rb + 8, kb0 + 4);
                ah[mt][0] = v0.x; al[mt][0] = v0.y;
                ah[mt][1] = v1.x; al[mt][1] = v1.y;
                ah[mt][2] = v2.x; al[mt][2] = v2.y;
                ah[mt][3] = v3.x; al[mt][3] = v3.y;
            }
#pragma unroll
            for (int nt = 0; nt < 4; ++nt) {
                const int nb = wN * 32 + nt * 8 + lr;
                uint2 w0 = sB[nb * KP + (kb0 ^ ((nb & 3) << 2))];
                uint2 w1 = sB[nb * KP + ((kb0 + 4) ^ ((nb & 3) << 2))];
                bh[nt][0] = w0.x; bl[nt][0] = w0.y;
                bh[nt][1] = w1.x; bl[nt][1] = w1.y;
            }
#pragma unroll
            for (int mt = 0; mt < 2; ++mt)
#pragma unroll
                for (int nt = 0; nt < 4; ++nt) {
                    mma_bf16(c[mt][nt], al[mt], bh[nt]);
                    mma_bf16(c[mt][nt], ah[mt], bl[nt]);
                    mma_bf16(c[mt][nt], ah[mt], bh[nt]);
                }
        }
    };

    // ---- main-pass chunk: A = s2, 3-stage B pipeline, ONE sync per k-block ----
    auto run_chunk = [&](const uint2* Bgc, float (&c)[2][4][4]) {
        const int KB = NDIM / KC;   // 16
        fillB(0, Bgc, NDIM / 2, 0); cp_commit();
        fillB(1, Bgc, NDIM / 2, 1); cp_commit();
        for (int kb = 0; kb < KB; ++kb) {
            cp_wait<1>();
            __syncthreads();
            if (kb + 2 < KB) fillB((kb + 2) % NBST, Bgc, NDIM / 2, kb + 2);
            cp_commit();
            const int kbase = kb * KP;
            mma_block([&](int r, int kp) {
                int cc = kbase + kp;
                return s2[r * 256 + (cc ^ ((r & 3) << 2))];
            }, &BstU[(kb % NBST) * BST_U2], c);
        }
        __syncthreads();
    };

    auto zero_acc = [&](float (&c)[2][4][4]) {
#pragma unroll
        for (int mt = 0; mt < 2; ++mt)
#pragma unroll
            for (int nt = 0; nt < 4; ++nt)
#pragma unroll
                for (int q = 0; q < 4; ++q) c[mt][nt][q] = 0.f;
    };

    // =========================== prestep =================================
    // WyD = y @ GW^T ; s2 = pack(softthr(WyD)).  A = yp via overlay stages,
    // 2-stage double-sync pipeline (A overlay lives in s2 second halves of
    // rows 0-15; h=0 epilogue writes only first halves, h=1 epilogue writes
    // second halves after its k-loop is done).
    {
        const uint2* Ag = yp + (size_t)r0 * (MDIM / 2);
        for (int h = 0; h < 2; ++h) {
            float c[2][4][4];
            zero_acc(c);
            const uint2* Bgc = GWp + (size_t)(h * NC) * (MDIM / 2);
            fillA_pre(0, Ag, 0);
            fillB(0, Bgc, MDIM / 2, 0);
            cp_commit();
            const int KB = MDIM / KC;   // 8
            for (int kb = 0; kb < KB; ++kb) {
                if (kb + 1 < KB) {
                    fillA_pre((kb + 1) & 1, Ag, kb + 1);
                    fillB((kb + 1) & 1, Bgc, MDIM / 2, kb + 1);
                    cp_commit();
                    cp_wait<1>();
                } else {
                    cp_wait<0>();
                }
                __syncthreads();
                const int st = kb & 1;
                mma_block([&](int r, int kp) {
                    return s2[a_idx(st, r * KP + (kp ^ ((r & 3) << 2)))];
                }, &BstU[st * BST_U2], c);
                __syncthreads();
            }
            // epilogue: WyD = u (fp32) ; s2 = pack(softthr(u))
#pragma unroll
            for (int mt = 0; mt < 2; ++mt)
#pragma unroll
                for (int nt = 0; nt < 4; ++nt) {
                    const int colc = wN * 32 + nt * 8 + 2 * lc;
#pragma unroll
                    for (int half = 0; half < 2; ++half) {
                        const int r = wM * 32 + mt * 16 + lr + half * 8;
                        const int col = h * NC + colc;
                        const size_t g = (size_t)(r0 + r) * NDIM + col;
                        float u0 = c[mt][nt][half * 2 + 0];
                        float u1 = c[mt][nt][half * 2 + 1];
                        *(float2*)&WyD[g] = make_float2(u0, u1);
                        const int cp = col >> 1;
                        s2[r * 256 + (cp ^ ((r & 3) << 2))] =
                            pack_split(softthr(u0, th), softthr(u1, th));
                    }
                }
            __syncthreads();
        }
    }

    // =========================== iterations ==============================
    for (int t = 1; t <= NITER; ++t) {
        float c[2][4][4];

        // ---- chunks 0,1: d_t cols -> out slab t (est staging) ----
        for (int h = 0; h < 2; ++h) {
            zero_acc(c);
            run_chunk(Bcatp + (size_t)(h * NC) * (NDIM / 2), c);
#pragma unroll
            for (int mt = 0; mt < 2; ++mt)
#pragma unroll
                for (int nt = 0; nt < 4; ++nt) {
                    const int colc = wN * 32 + nt * 8 + 2 * lc;
                    const int r = wM * 32 + mt * 16 + lr;
                    *(float2*)&est[r * PE + colc] = make_float2(c[mt][nt][0], c[mt][nt][1]);
                    *(float2*)&est[(r + 8) * PE + colc] = make_float2(c[mt][nt][2], c[mt][nt][3]);
                }
            __syncthreads();
            float* dst = out + (size_t)t * slab + (size_t)r0 * NDIM + h * NC;
            for (int i = tid; i < ROWS * (NC / 4); i += 512) {
                int r = i >> 6, c4 = i & 63;
                float4 v = *(float4*)&est[r * PE + c4 * 4];
                *(float4*)&dst[(size_t)r * NDIM + c4 * 4] = v;
            }
            __syncthreads();
        }

        if (t == NITER) break;

        // ---- chunk 2: u cols 0-255, raw fp32 -> Ulo scratch ----
        zero_acc(c);
        run_chunk(Bcatp + (size_t)(2 * NC) * (NDIM / 2), c);
#pragma unroll
        for (int mt = 0; mt < 2; ++mt)
#pragma unroll
            for (int nt = 0; nt < 4; ++nt) {
                const int colc = wN * 32 + nt * 8 + 2 * lc;
#pragma unroll
                for (int half = 0; half < 2; ++half) {
                    const int r = wM * 32 + mt * 16 + lr + half * 8;
                    *(float2*)&Ulo[(size_t)(r0 + r) * (NDIM / 2) + colc] =
                        make_float2(c[mt][nt][half * 2 + 0], c[mt][nt][half * 2 + 1]);
                }
            }
        __syncthreads();

        // ---- chunk 3: u cols 256-511 in regs -> s2 second halves ----
        zero_acc(c);
        run_chunk(Bcatp + (size_t)(3 * NC) * (NDIM / 2), c);
#pragma unroll
        for (int mt = 0; mt < 2; ++mt)
#pragma unroll
            for (int nt = 0; nt < 4; ++nt) {
                const int colc = wN * 32 + nt * 8 + 2 * lc;
#pragma unroll
                for (int half = 0; half < 2; ++half) {
                    const int r = wM * 32 + mt * 16 + lr + half * 8;
                    const size_t g = (size_t)(r0 + r) * NDIM + NC + colc;
                    float2 w = *(const float2*)&WyD[g];
                    float u0 = c[mt][nt][half * 2 + 0] + w.x;
                    float u1 = c[mt][nt][half * 2 + 1] + w.y;
                    const int cp = 128 + (colc >> 1);
                    s2[r * 256 + (cp ^ ((r & 3) << 2))] =
                        pack_split(softthr(u0, th), softthr(u1, th));
                }
            }

        // ---- consume Ulo -> s2 first halves ----
        for (int i = tid; i < ROWS * (NC / 4); i += 512) {
            int r = i >> 6, c4 = i & 63;
            float4 v = *(float4*)&Ulo[(size_t)(r0 + r) * (NDIM / 2) + c4 * 4];
            float4 w = *(float4*)&WyD[(size_t)(r0 + r) * NDIM + c4 * 4];
            float s0 = softthr(v.x + w.x, th);
            float s1 = softthr(v.y + w.y, th);
            float s2v = softthr(v.z + w.z, th);
            float s3 = softthr(v.w + w.w, th);
            uint2 p0 = pack_split(s0, s1);
            uint2 p1 = pack_split(s2v, s3);
            int cp = c4 * 2;
            int idx = r * 256 + (cp ^ ((r & 3) << 2));
            *(uint4*)&s2[idx] = make_uint4(p0.x, p0.y, p1.x, p1.y);
        }
        __syncthreads();
    }
}

// ---------------------------------------------------------------------------
// Host side
// ---------------------------------------------------------------------------
extern "C" void kernel_launch(void* const* d_in, const int* in_sizes, int n_in,
                              void* d_out, int out_size) {
    const float* y   = (const float*)d_in[0];
    const float* S   = (const float*)d_in[1];
    const float* W   = (const float*)d_in[2];
    const float* D   = (const float*)d_in[3];
    const float* thr = (const float*)d_in[4];
    float* out = (float*)d_out;

    void *pBcat, *pGW, *pyp, *pWyD, *pUlo, *pG1f;
    cudaGetSymbolAddress(&pBcat, g_Bcatp);
    cudaGetSymbolAddress(&pGW, g_GWp);
    cudaGetSymbolAddress(&pyp, g_yp);
    cudaGetSymbolAddress(&pWyD, g_WyD);
    cudaGetSymbolAddress(&pUlo, g_Ulo);
    cudaGetSymbolAddress(&pG1f, g_G1f);

    cudaFuncSetAttribute(k_ista, cudaFuncAttributeMaxDynamicSharedMemorySize, SMEM_BYTES);

    // Precompute: G1f = D@S (fp32); Bcat rows 0-511 = pack(D^T);
    // Bcat rows 512-1023 = pack(G1f @ D^T) = pack(D@S@D^T); GWp = pack(D@W); yp.
    k_small_gemm_f32<<<dim3(32, 32), dim3(16, 16)>>>(D, S, (float*)pG1f, NDIM, NDIM);
    k_transpose_pack<<<dim3(16, 32), dim3(16, 16)>>>(D, (uint2*)pBcat);
    k_abt_pack<<<dim3(32, 32), dim3(16, 16)>>>((const float*)pG1f, D,
                                               (uint2*)pBcat + (size_t)NDIM * (NDIM / 2));
    k_small_gemm_pack<<<dim3(16, 32), dim3(16, 16)>>>(D, W, (uint2*)pGW, MDIM, NDIM);
    k_split_pack<<<(B_ROWS * MDIM / 2) / 256, 256>>>(y, (uint2*)pyp);

    // One persistent kernel runs the whole recurrence.
    k_ista<<<B_ROWS / ROWS, 512, SMEM_BYTES>>>(
        thr, out, (const uint2*)pBcat, (const uint2*)pGW, (const uint2*)pyp,
        (float*)pWyD, (float*)pUlo);
}